// round 1
// baseline (speedup 1.0000x reference)
#include <cuda_runtime.h>
#include <cstdint>
#include <cstddef>

// Problem constants
constexpr int B   = 65536;
constexpr int T   = 30;
constexpr int H   = 64;
constexpr int G   = 256;   // 4*H, gate order i,f,g,o
constexpr int IN0 = 9;

constexpr int TPB0 = 256;  // layer0 threads (samples) per CTA
constexpr int TPB1 = 128;  // layer1 threads (samples) per CTA

// Scratch: layer0 outputs, layout [t][k][s]  (coalesced for both writer & reader)
__device__ float g_out0[(size_t)T * H * B];

// ---------------- f32x2 helpers (FFMA2 path, sm_100+) ----------------
__device__ __forceinline__ unsigned long long pack2(float a, float b) {
    unsigned long long r;
    asm("mov.b64 %0, {%1, %2};" : "=l"(r) : "f"(a), "f"(b));
    return r;
}
__device__ __forceinline__ void unpack2(unsigned long long v, float& a, float& b) {
    asm("mov.b64 {%0, %1}, %2;" : "=f"(a), "=f"(b) : "l"(v));
}
__device__ __forceinline__ unsigned long long fma2(unsigned long long a,
                                                   unsigned long long b,
                                                   unsigned long long c) {
    unsigned long long d;
    asm("fma.rn.f32x2 %0, %1, %2, %3;" : "=l"(d) : "l"(a), "l"(b), "l"(c));
    return d;
}

// Accurate-enough nonlinearities (~1e-6 rel err), cheap (1 MUFU.EX2 + 1 fast div)
__device__ __forceinline__ float sigf(float x) {
    return __fdividef(1.f, 1.f + __expf(-x));
}
__device__ __forceinline__ float tanh_(float x) {
    return __fdividef(2.f, 1.f + __expf(-2.f * x)) - 1.f;
}

// =====================================================================
// Layer 0: x[B][T][9] -> g_out0[t][k][s]
// =====================================================================
__global__ void __launch_bounds__(TPB0) lstm_layer0(
    const float* __restrict__ x,
    const float* __restrict__ Wih,   // [256][9]
    const float* __restrict__ Whh,   // [256][64]
    const float* __restrict__ bih,
    const float* __restrict__ bhh)
{
    extern __shared__ float sm[];
    float* s_wih  = sm;                       // [9][256]  transposed
    float* s_whh  = s_wih + IN0 * G;          // [64][256] transposed
    float* s_bias = s_whh + H * G;            // [256]
    float* s_h0   = s_bias + G;               // [64][TPB0]
    float* s_h1   = s_h0 + H * TPB0;          // [64][TPB0]

    const int tid = threadIdx.x;

    for (int idx = tid; idx < G * IN0; idx += TPB0) {
        int g = idx / IN0, i = idx - g * IN0;
        s_wih[i * G + g] = Wih[idx];
    }
    for (int idx = tid; idx < G * H; idx += TPB0) {
        int g = idx >> 6, k = idx & 63;
        s_whh[k * G + g] = Whh[idx];
    }
    for (int idx = tid; idx < G; idx += TPB0) s_bias[idx] = bih[idx] + bhh[idx];
#pragma unroll
    for (int k = 0; k < H; k++) s_h0[k * TPB0 + tid] = 0.f;
    __syncthreads();

    const int s = blockIdx.x * TPB0 + tid;
    const float* xp = x + (size_t)s * (T * IN0);

    float c[H];
#pragma unroll
    for (int k = 0; k < H; k++) c[k] = 0.f;

    float* hcur = s_h0;
    float* hnew = s_h1;

    for (int t = 0; t < T; t++) {
        float xr[IN0];
#pragma unroll
        for (int i = 0; i < IN0; i++) xr[i] = xp[t * IN0 + i];

#pragma unroll
        for (int jb = 0; jb < 8; jb++) {
            const int g0 = jb * 8;
            unsigned long long acc[16];
#pragma unroll
            for (int q = 0; q < 4; q++) {
                const ulonglong2* bp =
                    (const ulonglong2*)&s_bias[q * H + g0];
                ulonglong2 b0 = bp[0], b1 = bp[1];
                acc[q * 4 + 0] = b0.x; acc[q * 4 + 1] = b0.y;
                acc[q * 4 + 2] = b1.x; acc[q * 4 + 3] = b1.y;
            }
            // input projection (9 terms)
#pragma unroll
            for (int i = 0; i < IN0; i++) {
                unsigned long long x2 = pack2(xr[i], xr[i]);
                const float* wrow = &s_wih[i * G + g0];
#pragma unroll
                for (int q = 0; q < 4; q++) {
                    const ulonglong2* wv = (const ulonglong2*)&wrow[q * H];
                    ulonglong2 w0 = wv[0], w1 = wv[1];
                    acc[q * 4 + 0] = fma2(w0.x, x2, acc[q * 4 + 0]);
                    acc[q * 4 + 1] = fma2(w0.y, x2, acc[q * 4 + 1]);
                    acc[q * 4 + 2] = fma2(w1.x, x2, acc[q * 4 + 2]);
                    acc[q * 4 + 3] = fma2(w1.y, x2, acc[q * 4 + 3]);
                }
            }
            // recurrent part (64 terms)
#pragma unroll 2
            for (int k = 0; k < H; k++) {
                float hk = hcur[k * TPB0 + tid];
                unsigned long long h2 = pack2(hk, hk);
                const float* wrow = &s_whh[k * G + g0];
#pragma unroll
                for (int q = 0; q < 4; q++) {
                    const ulonglong2* wv = (const ulonglong2*)&wrow[q * H];
                    ulonglong2 w0 = wv[0], w1 = wv[1];
                    acc[q * 4 + 0] = fma2(w0.x, h2, acc[q * 4 + 0]);
                    acc[q * 4 + 1] = fma2(w0.y, h2, acc[q * 4 + 1]);
                    acc[q * 4 + 2] = fma2(w1.x, h2, acc[q * 4 + 2]);
                    acc[q * 4 + 3] = fma2(w1.y, h2, acc[q * 4 + 3]);
                }
            }
            // gate nonlinearities + state update for 8 units
#pragma unroll
            for (int u = 0; u < 8; u++) {
                const int p = u >> 1, lane = u & 1;
                float ga[4];
#pragma unroll
                for (int q = 0; q < 4; q++) {
                    float lo, hi;
                    unpack2(acc[q * 4 + p], lo, hi);
                    ga[q] = lane ? hi : lo;
                }
                float iv = sigf(ga[0]);
                float fv = sigf(ga[1]);
                float gv = tanh_(ga[2]);
                float ov = sigf(ga[3]);
                const int j = g0 + u;
                float cc = fv * c[j] + iv * gv;
                c[j] = cc;
                float hv = ov * tanh_(cc);
                hnew[j * TPB0 + tid] = hv;
                g_out0[((size_t)t * H + j) * B + s] = hv;
            }
        }
        float* tmp = hcur; hcur = hnew; hnew = tmp;
    }
}

// =====================================================================
// Layer 1: g_out0 -> LSTM -> LayerNorm(h_T) -> out[B][64]
// =====================================================================
__global__ void __launch_bounds__(TPB1) lstm_layer1(
    const float* __restrict__ Wih,   // [256][64]
    const float* __restrict__ Whh,   // [256][64]
    const float* __restrict__ bih,
    const float* __restrict__ bhh,
    const float* __restrict__ gamma,
    const float* __restrict__ beta,
    float* __restrict__ out)
{
    extern __shared__ float sm[];
    float* s_wih  = sm;                       // [64][256]
    float* s_whh  = s_wih + H * G;            // [64][256]
    float* s_bias = s_whh + H * G;            // [256]
    float* s_x    = s_bias + G;               // [64][TPB1]
    float* s_h0   = s_x + H * TPB1;           // [64][TPB1]
    float* s_h1   = s_h0 + H * TPB1;          // [64][TPB1]

    const int tid = threadIdx.x;

    for (int idx = tid; idx < G * H; idx += TPB1) {
        int g = idx >> 6, k = idx & 63;
        s_wih[k * G + g] = Wih[idx];
        s_whh[k * G + g] = Whh[idx];
    }
    for (int idx = tid; idx < G; idx += TPB1) s_bias[idx] = bih[idx] + bhh[idx];
#pragma unroll
    for (int k = 0; k < H; k++) s_h0[k * TPB1 + tid] = 0.f;
    __syncthreads();

    const int s = blockIdx.x * TPB1 + tid;

    float c[H];
#pragma unroll
    for (int k = 0; k < H; k++) c[k] = 0.f;

    float* hcur = s_h0;
    float* hnew = s_h1;

    for (int t = 0; t < T; t++) {
        // stage this timestep's layer-0 output (coalesced LDG)
        const float* src = g_out0 + (size_t)t * H * B + s;
#pragma unroll 8
        for (int k = 0; k < H; k++) s_x[k * TPB1 + tid] = src[(size_t)k * B];

#pragma unroll
        for (int jb = 0; jb < 8; jb++) {
            const int g0 = jb * 8;
            unsigned long long acc[16];
#pragma unroll
            for (int q = 0; q < 4; q++) {
                const ulonglong2* bp =
                    (const ulonglong2*)&s_bias[q * H + g0];
                ulonglong2 b0 = bp[0], b1 = bp[1];
                acc[q * 4 + 0] = b0.x; acc[q * 4 + 1] = b0.y;
                acc[q * 4 + 2] = b1.x; acc[q * 4 + 3] = b1.y;
            }
#pragma unroll 2
            for (int k = 0; k < H; k++) {
                float xk = s_x[k * TPB1 + tid];
                float hk = hcur[k * TPB1 + tid];
                unsigned long long x2 = pack2(xk, xk);
                unsigned long long h2 = pack2(hk, hk);
                const float* wi = &s_wih[k * G + g0];
                const float* wh = &s_whh[k * G + g0];
#pragma unroll
                for (int q = 0; q < 4; q++) {
                    const ulonglong2* wiv = (const ulonglong2*)&wi[q * H];
                    const ulonglong2* whv = (const ulonglong2*)&wh[q * H];
                    ulonglong2 a0 = wiv[0], a1 = wiv[1];
                    ulonglong2 b0 = whv[0], b1 = whv[1];
                    acc[q * 4 + 0] = fma2(a0.x, x2, acc[q * 4 + 0]);
                    acc[q * 4 + 1] = fma2(a0.y, x2, acc[q * 4 + 1]);
                    acc[q * 4 + 2] = fma2(a1.x, x2, acc[q * 4 + 2]);
                    acc[q * 4 + 3] = fma2(a1.y, x2, acc[q * 4 + 3]);
                    acc[q * 4 + 0] = fma2(b0.x, h2, acc[q * 4 + 0]);
                    acc[q * 4 + 1] = fma2(b0.y, h2, acc[q * 4 + 1]);
                    acc[q * 4 + 2] = fma2(b1.x, h2, acc[q * 4 + 2]);
                    acc[q * 4 + 3] = fma2(b1.y, h2, acc[q * 4 + 3]);
                }
            }
#pragma unroll
            for (int u = 0; u < 8; u++) {
                const int p = u >> 1, lane = u & 1;
                float ga[4];
#pragma unroll
                for (int q = 0; q < 4; q++) {
                    float lo, hi;
                    unpack2(acc[q * 4 + p], lo, hi);
                    ga[q] = lane ? hi : lo;
                }
                float iv = sigf(ga[0]);
                float fv = sigf(ga[1]);
                float gv = tanh_(ga[2]);
                float ov = sigf(ga[3]);
                const int j = g0 + u;
                float cc = fv * c[j] + iv * gv;
                c[j] = cc;
                hnew[j * TPB1 + tid] = ov * tanh_(cc);
            }
        }
        float* tmp = hcur; hcur = hnew; hnew = tmp;
    }

    // LayerNorm over final hidden state (64 values, thread-local)
    float sum = 0.f;
#pragma unroll
    for (int k = 0; k < H; k++) sum += hcur[k * TPB1 + tid];
    float mean = sum * (1.f / 64.f);
    float vs = 0.f;
#pragma unroll
    for (int k = 0; k < H; k++) {
        float d = hcur[k * TPB1 + tid] - mean;
        vs += d * d;
    }
    float rstd = rsqrtf(vs * (1.f / 64.f) + 1e-5f);
#pragma unroll
    for (int k = 0; k < H; k++) {
        float v = (hcur[k * TPB1 + tid] - mean) * rstd;
        out[(size_t)s * H + k] = v * gamma[k] + beta[k];
    }
}

// =====================================================================
extern "C" void kernel_launch(void* const* d_in, const int* in_sizes, int n_in,
                              void* d_out, int out_size) {
    (void)in_sizes; (void)n_in; (void)out_size;
    const float* x     = (const float*)d_in[0];
    const float* Wih0  = (const float*)d_in[1];
    const float* Whh0  = (const float*)d_in[2];
    const float* bih0  = (const float*)d_in[3];
    const float* bhh0  = (const float*)d_in[4];
    const float* Wih1  = (const float*)d_in[5];
    const float* Whh1  = (const float*)d_in[6];
    const float* bih1  = (const float*)d_in[7];
    const float* bhh1  = (const float*)d_in[8];
    const float* gamma = (const float*)d_in[9];
    const float* beta  = (const float*)d_in[10];
    float* out = (float*)d_out;

    const size_t smem0 =
        (size_t)(IN0 * G + H * G + G + 2 * H * TPB0) * sizeof(float); // 206,848 B
    const size_t smem1 =
        (size_t)(2 * H * G + G + 3 * H * TPB1) * sizeof(float);       // 230,400 B

    cudaFuncSetAttribute(lstm_layer0, cudaFuncAttributeMaxDynamicSharedMemorySize,
                         (int)smem0);
    cudaFuncSetAttribute(lstm_layer1, cudaFuncAttributeMaxDynamicSharedMemorySize,
                         (int)smem1);

    lstm_layer0<<<B / TPB0, TPB0, smem0>>>(x, Wih0, Whh0, bih0, bhh0);
    lstm_layer1<<<B / TPB1, TPB1, smem1>>>(Wih1, Whh1, bih1, bhh1, gamma, beta, out);
}